// round 7
// baseline (speedup 1.0000x reference)
#include <cuda_runtime.h>
#include <math.h>

#define B_ 4
#define T_ 1024
#define C_ 1024
#define H_ 16
#define D_ 64
#define HD_ (H_*D_)

// Scratch (allocation-free rule: __device__ globals)
__device__ float g_q[(size_t)B_*H_*T_*D_];
__device__ float g_k[(size_t)B_*H_*T_*D_];
__device__ float g_v[(size_t)B_*H_*T_*D_];
__device__ float g_att[(size_t)B_*T_*HD_];   // [B, T, H, D] = [B, T, HD]

// ---------------------------------------------------------------------------
// fp32 -> tf32 (round to nearest) as raw bits
// ---------------------------------------------------------------------------
__device__ __forceinline__ float f2tf32(float f) {
    unsigned u;
    asm("cvt.rna.tf32.f32 %0, %1;" : "=r"(u) : "f"(f));
    return __uint_as_float(u);
}

__device__ __forceinline__ void mma_tf32(float c[4], const unsigned a[4],
                                         const unsigned b[2]) {
    asm("mma.sync.aligned.m16n8k8.row.col.f32.tf32.tf32.f32 "
        "{%0,%1,%2,%3}, {%4,%5,%6,%7}, {%8,%9}, {%0,%1,%2,%3};"
        : "+f"(c[0]), "+f"(c[1]), "+f"(c[2]), "+f"(c[3])
        : "r"(a[0]), "r"(a[1]), "r"(a[2]), "r"(a[3]), "r"(b[0]), "r"(b[1]));
}

// ---------------------------------------------------------------------------
// TF32 tensor-core GEMM tile: C[m0:m0+128, n0:n0+64] = A @ B (+bias)
// (unchanged from R3 — passing)
// ---------------------------------------------------------------------------
__device__ __forceinline__ void gemm128x64_tf32(
    const float* __restrict__ A, int lda,
    const float* __restrict__ Bm, int ldb,
    const float* __restrict__ bias,
    float* __restrict__ Cm, int ldc,
    int Kdim, int m0, int n0)
{
    __shared__ float As[128][36];
    __shared__ float Bs[32][72];

    const int tid  = threadIdx.x;
    const int warp = tid >> 5;
    const int lane = tid & 31;
    const int wm0  = (warp >> 1) * 32;
    const int wn0  = (warp & 1) * 32;
    const int gid  = lane >> 2;
    const int tig  = lane & 3;

    const int a_row = tid >> 3;
    const int a_cg  = (tid & 7) * 4;
    const int b_row = tid >> 4;
    const int b_cg  = (tid & 15) * 4;

    float4 areg[4], breg[2];

    #pragma unroll
    for (int i = 0; i < 4; i++)
        areg[i] = *(const float4*)(A + (size_t)(m0 + a_row + 32 * i) * lda + a_cg);
    #pragma unroll
    for (int i = 0; i < 2; i++)
        breg[i] = *(const float4*)(Bm + (size_t)(b_row + 16 * i) * ldb + n0 + b_cg);

    float acc[2][4][4];
    #pragma unroll
    for (int i = 0; i < 2; i++)
        #pragma unroll
        for (int j = 0; j < 4; j++)
            #pragma unroll
            for (int r = 0; r < 4; r++) acc[i][j][r] = 0.0f;

    for (int kt = 0; kt < Kdim; kt += 32) {
        #pragma unroll
        for (int i = 0; i < 4; i++) {
            float* p = &As[a_row + 32 * i][a_cg];
            p[0] = f2tf32(areg[i].x);
            p[1] = f2tf32(areg[i].y);
            p[2] = f2tf32(areg[i].z);
            p[3] = f2tf32(areg[i].w);
        }
        #pragma unroll
        for (int i = 0; i < 2; i++) {
            float* p = &Bs[b_row + 16 * i][b_cg];
            p[0] = f2tf32(breg[i].x);
            p[1] = f2tf32(breg[i].y);
            p[2] = f2tf32(breg[i].z);
            p[3] = f2tf32(breg[i].w);
        }
        __syncthreads();

        if (kt + 32 < Kdim) {
            #pragma unroll
            for (int i = 0; i < 4; i++)
                areg[i] = *(const float4*)(A + (size_t)(m0 + a_row + 32 * i) * lda + kt + 32 + a_cg);
            #pragma unroll
            for (int i = 0; i < 2; i++)
                breg[i] = *(const float4*)(Bm + (size_t)(kt + 32 + b_row + 16 * i) * ldb + n0 + b_cg);
        }

        #pragma unroll
        for (int ks = 0; ks < 4; ks++) {
            const int k0 = ks * 8;
            unsigned a[2][4], b[4][2];
            #pragma unroll
            for (int i = 0; i < 2; i++) {
                const int r = wm0 + i * 16 + gid;
                a[i][0] = __float_as_uint(As[r    ][k0 + tig    ]);
                a[i][1] = __float_as_uint(As[r + 8][k0 + tig    ]);
                a[i][2] = __float_as_uint(As[r    ][k0 + tig + 4]);
                a[i][3] = __float_as_uint(As[r + 8][k0 + tig + 4]);
            }
            #pragma unroll
            for (int j = 0; j < 4; j++) {
                const int n = wn0 + j * 8 + gid;
                b[j][0] = __float_as_uint(Bs[k0 + tig    ][n]);
                b[j][1] = __float_as_uint(Bs[k0 + tig + 4][n]);
            }
            #pragma unroll
            for (int i = 0; i < 2; i++)
                #pragma unroll
                for (int j = 0; j < 4; j++)
                    mma_tf32(acc[i][j], a[i], b[j]);
        }
        __syncthreads();
    }

    #pragma unroll
    for (int i = 0; i < 2; i++) {
        const int r = m0 + wm0 + i * 16 + gid;
        #pragma unroll
        for (int j = 0; j < 4; j++) {
            const int c = n0 + wn0 + j * 8 + 2 * tig;
            float bx = 0.f, by = 0.f;
            if (bias) { bx = bias[c]; by = bias[c + 1]; }
            float2 o0 = make_float2(acc[i][j][0] + bx, acc[i][j][1] + by);
            float2 o1 = make_float2(acc[i][j][2] + bx, acc[i][j][3] + by);
            *(float2*)(Cm + (size_t)r * ldc + c) = o0;
            *(float2*)(Cm + (size_t)(r + 8) * ldc + c) = o1;
        }
    }
}

// ---------------------------------------------------------------------------
// Kernel 1: QKV projections (tensor cores). grid=(T/128, B*H, 3), block=256
// ---------------------------------------------------------------------------
__global__ __launch_bounds__(256) void qkv_kernel(const float* __restrict__ x,
                                                  const float* __restrict__ Wq,
                                                  const float* __restrict__ Wk,
                                                  const float* __restrict__ Wv)
{
    const int bh = blockIdx.y;
    const int b = bh >> 4;
    const int h = bh & 15;
    const int which = blockIdx.z;
    const float* W = (which == 0 ? Wq : (which == 1 ? Wk : Wv)) + (size_t)h * C_ * D_;
    float* dst = (which == 0 ? g_q : (which == 1 ? g_k : g_v)) + (size_t)bh * T_ * D_;
    gemm128x64_tf32(x + (size_t)b * T_ * C_, C_, W, D_, nullptr, dst, D_, C_,
                    blockIdx.x * 128, 0);
}

// ---------------------------------------------------------------------------
// Kernel 2: causal flash attention on tensor cores (tf32 m16n8k8).
// grid=(T/64, B*H), block=128 (4 warps, each m16 x n64).
// smem: Kst[64][72] (d-major), Vs[64][72] (natural), Pst[64][72] (P / Q stage)
// ---------------------------------------------------------------------------
#define SP 72
__global__ __launch_bounds__(128) void attn_kernel()
{
    extern __shared__ float sm[];
    float* Kst = sm;              // [64][SP]  Kst[d][s]
    float* Vs  = sm + 64 * SP;    // [64][SP]  Vs[s][d]
    float* Pst = sm + 128 * SP;   // [64][SP]  P rows (also Q staging)

    const int qt = (int)gridDim.x - 1 - (int)blockIdx.x;  // long CTAs first
    const int bh = blockIdx.y;
    const int b = bh >> 4;
    const int h = bh & 15;
    const float* qg = g_q + (size_t)bh * T_ * D_;
    const float* kg = g_k + (size_t)bh * T_ * D_;
    const float* vg = g_v + (size_t)bh * T_ * D_;

    const int tid  = threadIdx.x;
    const int warp = tid >> 5;
    const int lane = tid & 31;
    const int gid  = lane >> 2;
    const int tig  = lane & 3;
    const int wm   = warp * 16;
    const int lr   = tid >> 1;          // 0..63
    const int lc0  = (tid & 1) * 32;    // column half

    // Stage Q tile into Pst (scaled, tf32), then pull A-fragments to registers
    #pragma unroll
    for (int g = 0; g < 8; g++) {
        const int c = lc0 + g * 4;
        float4 qv = *(const float4*)(qg + (size_t)(qt * 64 + lr) * D_ + c);
        float* p = &Pst[lr * SP + c];
        p[0] = f2tf32(qv.x * 0.125f);
        p[1] = f2tf32(qv.y * 0.125f);
        p[2] = f2tf32(qv.z * 0.125f);
        p[3] = f2tf32(qv.w * 0.125f);
    }
    __syncthreads();

    unsigned qf[8][4];
    #pragma unroll
    for (int ks = 0; ks < 8; ks++) {
        qf[ks][0] = __float_as_uint(Pst[(wm + gid    ) * SP + ks * 8 + tig    ]);
        qf[ks][1] = __float_as_uint(Pst[(wm + gid + 8) * SP + ks * 8 + tig    ]);
        qf[ks][2] = __float_as_uint(Pst[(wm + gid    ) * SP + ks * 8 + tig + 4]);
        qf[ks][3] = __float_as_uint(Pst[(wm + gid + 8) * SP + ks * 8 + tig + 4]);
    }

    float oacc[8][4];
    #pragma unroll
    for (int j = 0; j < 8; j++)
        #pragma unroll
        for (int r = 0; r < 4; r++) oacc[j][r] = 0.0f;
    float m0 = -1e30f, m1 = -1e30f, l0 = 0.0f, l1 = 0.0f;

    for (int kt = 0; kt <= qt; ++kt) {
        __syncthreads();  // prev-iter Kst/Vs/Pst readers done (also Q staging)
        #pragma unroll
        for (int g = 0; g < 8; g++) {
            const int c = lc0 + g * 4;
            float4 kv = *(const float4*)(kg + (size_t)(kt * 64 + lr) * D_ + c);
            Kst[(c + 0) * SP + lr] = f2tf32(kv.x);
            Kst[(c + 1) * SP + lr] = f2tf32(kv.y);
            Kst[(c + 2) * SP + lr] = f2tf32(kv.z);
            Kst[(c + 3) * SP + lr] = f2tf32(kv.w);
            float4 vv = *(const float4*)(vg + (size_t)(kt * 64 + lr) * D_ + c);
            float* p = &Vs[lr * SP + c];
            p[0] = f2tf32(vv.x);
            p[1] = f2tf32(vv.y);
            p[2] = f2tf32(vv.z);
            p[3] = f2tf32(vv.w);
        }
        __syncthreads();

        // S = Q @ K^T
        float sacc[8][4];
        #pragma unroll
        for (int j = 0; j < 8; j++)
            #pragma unroll
            for (int r = 0; r < 4; r++) sacc[j][r] = 0.0f;

        #pragma unroll
        for (int ks = 0; ks < 8; ks++) {
            unsigned bf[8][2];
            #pragma unroll
            for (int j = 0; j < 8; j++) {
                bf[j][0] = __float_as_uint(Kst[(ks * 8 + tig    ) * SP + j * 8 + gid]);
                bf[j][1] = __float_as_uint(Kst[(ks * 8 + tig + 4) * SP + j * 8 + gid]);
            }
            #pragma unroll
            for (int j = 0; j < 8; j++)
                mma_tf32(sacc[j], qf[ks], bf[j]);
        }

        // causal mask (diagonal tile only; BQ == BK == 64, same offset)
        if (kt == qt) {
            #pragma unroll
            for (int j = 0; j < 8; j++) {
                const int n0c = j * 8 + 2 * tig;
                if (n0c     > wm + gid    ) sacc[j][0] = -1e30f;
                if (n0c + 1 > wm + gid    ) sacc[j][1] = -1e30f;
                if (n0c     > wm + gid + 8) sacc[j][2] = -1e30f;
                if (n0c + 1 > wm + gid + 8) sacc[j][3] = -1e30f;
            }
        }

        // online softmax (rows gid and gid+8; reduction over tig lanes)
        float mt0 = -1e30f, mt1 = -1e30f;
        #pragma unroll
        for (int j = 0; j < 8; j++) {
            mt0 = fmaxf(mt0, fmaxf(sacc[j][0], sacc[j][1]));
            mt1 = fmaxf(mt1, fmaxf(sacc[j][2], sacc[j][3]));
        }
        mt0 = fmaxf(mt0, __shfl_xor_sync(0xffffffffu, mt0, 1));
        mt0 = fmaxf(mt0, __shfl_xor_sync(0xffffffffu, mt0, 2));
        mt1 = fmaxf(mt1, __shfl_xor_sync(0xffffffffu, mt1, 1));
        mt1 = fmaxf(mt1, __shfl_xor_sync(0xffffffffu, mt1, 2));

        const float mn0 = fmaxf(m0, mt0);
        const float mn1 = fmaxf(m1, mt1);
        const float a0 = __expf(m0 - mn0);
        const float a1 = __expf(m1 - mn1);
        float ls0 = 0.0f, ls1 = 0.0f;

        #pragma unroll
        for (int j = 0; j < 8; j++) {
            const float p00 = __expf(sacc[j][0] - mn0);
            const float p01 = __expf(sacc[j][1] - mn0);
            const float p10 = __expf(sacc[j][2] - mn1);
            const float p11 = __expf(sacc[j][3] - mn1);
            ls0 += p00 + p01;
            ls1 += p10 + p11;
            const int c = j * 8 + 2 * tig;
            Pst[(wm + gid    ) * SP + c    ] = f2tf32(p00);
            Pst[(wm + gid    ) * SP + c + 1] = f2tf32(p01);
            Pst[(wm + gid + 8) * SP + c    ] = f2tf32(p10);
            Pst[(wm + gid + 8) * SP + c + 1] = f2tf32(p11);
            oacc[j][0] *= a0; oacc[j][1] *= a0;
            oacc[j][2] *= a1; oacc[j][3] *= a1;
        }
        ls0 += __shfl_xor_sync(0xffffffffu, ls0, 1);
        ls0 += __shfl_xor_sync(0xffffffffu, ls0, 2);
        ls1 += __shfl_xor_sync(0xffffffffu, ls1, 1);
        ls1 += __shfl_xor_sync(0xffffffffu, ls1, 2);
        l0 = l0 * a0 + ls0;
        l1 = l1 * a1 + ls1;
        m0 = mn0;
        m1 = mn1;
        __syncwarp();  // P rows are warp-private: warp sync suffices

        // O += P @ V
        #pragma unroll
        for (int ks = 0; ks < 8; ks++) {
            unsigned af[4];
            af[0] = __float_as_uint(Pst[(wm + gid    ) * SP + ks * 8 + tig    ]);
            af[1] = __float_as_uint(Pst[(wm + gid + 8) * SP + ks * 8 + tig    ]);
            af[2] = __float_as_uint(Pst[(wm + gid    ) * SP + ks * 8 + tig + 4]);
            af[3] = __float_as_uint(Pst[(wm + gid + 8) * SP + ks * 8 + tig + 4]);
            unsigned bf[8][2];
            #pragma unroll
            for (int j = 0; j < 8; j++) {
                bf[j][0] = __float_as_uint(Vs[(ks * 8 + tig    ) * SP + j * 8 + gid]);
                bf[j][1] = __float_as_uint(Vs[(ks * 8 + tig + 4) * SP + j * 8 + gid]);
            }
            #pragma unroll
            for (int j = 0; j < 8; j++)
                mma_tf32(oacc[j], af, bf[j]);
        }
    }

    // epilogue: normalize, write [B, T, H, D]
    const float i0 = 1.0f / l0;
    const float i1 = 1.0f / l1;
    const int r0 = qt * 64 + wm + gid;
    #pragma unroll
    for (int j = 0; j < 8; j++) {
        const int c = j * 8 + 2 * tig;
        float2 v0 = make_float2(oacc[j][0] * i0, oacc[j][1] * i0);
        float2 v1 = make_float2(oacc[j][2] * i1, oacc[j][3] * i1);
        *(float2*)(g_att + ((size_t)(b * T_ + r0    ) * H_ + h) * D_ + c) = v0;
        *(float2*)(g_att + ((size_t)(b * T_ + r0 + 8) * H_ + h) * D_ + c) = v1;
    }
}

// ---------------------------------------------------------------------------
// Kernel 3: output projection (tensor cores). grid=(C/64, B*T/128), block=256
// ---------------------------------------------------------------------------
__global__ __launch_bounds__(256) void proj_kernel(const float* __restrict__ Wp,
                                                   const float* __restrict__ bp,
                                                   float* __restrict__ out)
{
    gemm128x64_tf32(g_att, HD_, Wp, C_, bp, out, C_, HD_,
                    blockIdx.y * 128, blockIdx.x * 64);
}

// ---------------------------------------------------------------------------
extern "C" void kernel_launch(void* const* d_in, const int* in_sizes, int n_in,
                              void* d_out, int out_size)
{
    const float* x  = (const float*)d_in[0];
    const float* Wq = (const float*)d_in[1];
    const float* Wk = (const float*)d_in[2];
    const float* Wv = (const float*)d_in[3];
    const float* Wp = (const float*)d_in[4];
    const float* bp = (const float*)d_in[5];
    float* out = (float*)d_out;

    (void)in_sizes; (void)n_in; (void)out_size;

    // QKV projections (tensor cores)
    {
        dim3 grid(T_ / 128, B_ * H_, 3);
        qkv_kernel<<<grid, 256>>>(x, Wq, Wk, Wv);
    }

    // Attention (tensor cores, 54 KB dynamic smem)
    {
        const int smem = 3 * 64 * SP * sizeof(float);
        cudaFuncSetAttribute(attn_kernel,
                             cudaFuncAttributeMaxDynamicSharedMemorySize, smem);
        dim3 grid(T_ / 64, B_ * H_);
        attn_kernel<<<grid, 128, smem>>>();
    }

    // Output projection (tensor cores)
    {
        dim3 grid(C_ / 64, (B_ * T_) / 128);
        proj_kernel<<<grid, 256>>>(Wp, bp, out);
    }
}

// round 8
// speedup vs baseline: 1.1437x; 1.1437x over previous
#include <cuda_runtime.h>
#include <math.h>

#define B_ 4
#define T_ 1024
#define C_ 1024
#define H_ 16
#define D_ 64
#define HD_ (H_*D_)

// Scratch (allocation-free rule: __device__ globals)
__device__ float g_q[(size_t)B_*H_*T_*D_];
__device__ float g_k[(size_t)B_*H_*T_*D_];
__device__ float g_v[(size_t)B_*H_*T_*D_];
__device__ float g_att[(size_t)B_*T_*HD_];   // [B, T, H, D] = [B, T, HD]

// ---------------------------------------------------------------------------
__device__ __forceinline__ float f2tf32(float f) {
    unsigned u;
    asm("cvt.rna.tf32.f32 %0, %1;" : "=r"(u) : "f"(f));
    return __uint_as_float(u);
}

__device__ __forceinline__ void mma_tf32(float c[4], const unsigned a[4],
                                         const unsigned b[2]) {
    asm("mma.sync.aligned.m16n8k8.row.col.f32.tf32.tf32.f32 "
        "{%0,%1,%2,%3}, {%4,%5,%6,%7}, {%8,%9}, {%0,%1,%2,%3};"
        : "+f"(c[0]), "+f"(c[1]), "+f"(c[2]), "+f"(c[3])
        : "r"(a[0]), "r"(a[1]), "r"(a[2]), "r"(a[3]), "r"(b[0]), "r"(b[1]));
}

// ---------------------------------------------------------------------------
// TF32 GEMM tile, double-buffered smem: C[m0:+128, n0:+64] = A @ B (+bias)
// Dynamic smem: As[2][128][36] then Bs[2][32][72]  (55296 bytes)
// 256 threads = 8 warps, warp tile 32x32, BK=32, 1 syncthreads/iter.
// ---------------------------------------------------------------------------
#define AS_ELEMS (128*36)
#define BS_ELEMS (32*72)
#define GEMM_SMEM ((2*AS_ELEMS + 2*BS_ELEMS) * 4)

__device__ __forceinline__ void gemm128x64_tf32(
    const float* __restrict__ A, int lda,
    const float* __restrict__ Bm, int ldb,
    const float* __restrict__ bias,
    float* __restrict__ Cm, int ldc,
    int Kdim, int m0, int n0, float* sm)
{
    float* AsBase = sm;                    // [2][128][36]
    float* BsBase = sm + 2 * AS_ELEMS;     // [2][32][72]

    const int tid  = threadIdx.x;
    const int warp = tid >> 5;
    const int lane = tid & 31;
    const int wm0  = (warp >> 1) * 32;
    const int wn0  = (warp & 1) * 32;
    const int gid  = lane >> 2;
    const int tig  = lane & 3;

    const int a_row = tid >> 3;
    const int a_cg  = (tid & 7) * 4;
    const int b_row = tid >> 4;
    const int b_cg  = (tid & 15) * 4;

    float4 areg[4], breg[2];

    // prefetch tile 0 and stage into buffer 0
    #pragma unroll
    for (int i = 0; i < 4; i++)
        areg[i] = *(const float4*)(A + (size_t)(m0 + a_row + 32 * i) * lda + a_cg);
    #pragma unroll
    for (int i = 0; i < 2; i++)
        breg[i] = *(const float4*)(Bm + (size_t)(b_row + 16 * i) * ldb + n0 + b_cg);

    #pragma unroll
    for (int i = 0; i < 4; i++) {
        float* p = AsBase + (a_row + 32 * i) * 36 + a_cg;
        p[0] = f2tf32(areg[i].x); p[1] = f2tf32(areg[i].y);
        p[2] = f2tf32(areg[i].z); p[3] = f2tf32(areg[i].w);
    }
    #pragma unroll
    for (int i = 0; i < 2; i++) {
        float* p = BsBase + (b_row + 16 * i) * 72 + b_cg;
        p[0] = f2tf32(breg[i].x); p[1] = f2tf32(breg[i].y);
        p[2] = f2tf32(breg[i].z); p[3] = f2tf32(breg[i].w);
    }
    __syncthreads();

    float acc[2][4][4];
    #pragma unroll
    for (int i = 0; i < 2; i++)
        #pragma unroll
        for (int j = 0; j < 4; j++)
            #pragma unroll
            for (int r = 0; r < 4; r++) acc[i][j][r] = 0.0f;

    for (int kt = 0; kt < Kdim; kt += 32) {
        const int cur = (kt >> 5) & 1;
        const bool more = (kt + 32 < Kdim);
        float* As = AsBase + cur * AS_ELEMS;
        float* Bs = BsBase + cur * BS_ELEMS;

        if (more) {
            #pragma unroll
            for (int i = 0; i < 4; i++)
                areg[i] = *(const float4*)(A + (size_t)(m0 + a_row + 32 * i) * lda + kt + 32 + a_cg);
            #pragma unroll
            for (int i = 0; i < 2; i++)
                breg[i] = *(const float4*)(Bm + (size_t)(kt + 32 + b_row + 16 * i) * ldb + n0 + b_cg);
        }

        #pragma unroll
        for (int ks = 0; ks < 4; ks++) {
            const int k0 = ks * 8;
            unsigned a[2][4], b[4][2];
            #pragma unroll
            for (int i = 0; i < 2; i++) {
                const int r = wm0 + i * 16 + gid;
                a[i][0] = __float_as_uint(As[(r    ) * 36 + k0 + tig    ]);
                a[i][1] = __float_as_uint(As[(r + 8) * 36 + k0 + tig    ]);
                a[i][2] = __float_as_uint(As[(r    ) * 36 + k0 + tig + 4]);
                a[i][3] = __float_as_uint(As[(r + 8) * 36 + k0 + tig + 4]);
            }
            #pragma unroll
            for (int j = 0; j < 4; j++) {
                const int n = wn0 + j * 8 + gid;
                b[j][0] = __float_as_uint(Bs[(k0 + tig    ) * 72 + n]);
                b[j][1] = __float_as_uint(Bs[(k0 + tig + 4) * 72 + n]);
            }
            #pragma unroll
            for (int i = 0; i < 2; i++)
                #pragma unroll
                for (int j = 0; j < 4; j++)
                    mma_tf32(acc[i][j], a[i], b[j]);
        }

        if (more) {
            float* An = AsBase + (cur ^ 1) * AS_ELEMS;
            float* Bn = BsBase + (cur ^ 1) * BS_ELEMS;
            #pragma unroll
            for (int i = 0; i < 4; i++) {
                float* p = An + (a_row + 32 * i) * 36 + a_cg;
                p[0] = f2tf32(areg[i].x); p[1] = f2tf32(areg[i].y);
                p[2] = f2tf32(areg[i].z); p[3] = f2tf32(areg[i].w);
            }
            #pragma unroll
            for (int i = 0; i < 2; i++) {
                float* p = Bn + (b_row + 16 * i) * 72 + b_cg;
                p[0] = f2tf32(breg[i].x); p[1] = f2tf32(breg[i].y);
                p[2] = f2tf32(breg[i].z); p[3] = f2tf32(breg[i].w);
            }
        }
        __syncthreads();
    }

    #pragma unroll
    for (int i = 0; i < 2; i++) {
        const int r = m0 + wm0 + i * 16 + gid;
        #pragma unroll
        for (int j = 0; j < 4; j++) {
            const int c = n0 + wn0 + j * 8 + 2 * tig;
            float bx = 0.f, by = 0.f;
            if (bias) { bx = bias[c]; by = bias[c + 1]; }
            float2 o0 = make_float2(acc[i][j][0] + bx, acc[i][j][1] + by);
            float2 o1 = make_float2(acc[i][j][2] + bx, acc[i][j][3] + by);
            *(float2*)(Cm + (size_t)r * ldc + c) = o0;
            *(float2*)(Cm + (size_t)(r + 8) * ldc + c) = o1;
        }
    }
}

// ---------------------------------------------------------------------------
// Kernel 1: QKV projections. grid=(T/128, B*H, 3), block=256
// ---------------------------------------------------------------------------
__global__ __launch_bounds__(256) void qkv_kernel(const float* __restrict__ x,
                                                  const float* __restrict__ Wq,
                                                  const float* __restrict__ Wk,
                                                  const float* __restrict__ Wv)
{
    extern __shared__ float sm[];
    const int bh = blockIdx.y;
    const int b = bh >> 4;
    const int h = bh & 15;
    const int which = blockIdx.z;
    const float* W = (which == 0 ? Wq : (which == 1 ? Wk : Wv)) + (size_t)h * C_ * D_;
    float* dst = (which == 0 ? g_q : (which == 1 ? g_k : g_v)) + (size_t)bh * T_ * D_;
    gemm128x64_tf32(x + (size_t)b * T_ * C_, C_, W, D_, nullptr, dst, D_, C_,
                    blockIdx.x * 128, 0, sm);
}

// ---------------------------------------------------------------------------
// Kernel 2: causal flash attention, tf32 m16n8k8, BQ=128 (8 warps).
// grid=(T/128, B*H), block=256.
// smem: Kst[64][72] d-major, Vs[64][72] natural, Pst[128][72] (P / Q stage)
// ---------------------------------------------------------------------------
#define SP 72
#define ATTN_SMEM ((64*SP + 64*SP + 128*SP) * 4)

__global__ __launch_bounds__(256) void attn_kernel()
{
    extern __shared__ float sm[];
    float* Kst = sm;              // [64][SP]  Kst[d][s]
    float* Vs  = sm + 64 * SP;    // [64][SP]  Vs[s][d]
    float* Pst = sm + 128 * SP;   // [128][SP] P rows (also Q staging)

    const int qt = (int)gridDim.x - 1 - (int)blockIdx.x;  // long CTAs first
    const int bh = blockIdx.y;
    const int b = bh >> 4;
    const int h = bh & 15;
    const float* qg = g_q + (size_t)bh * T_ * D_;
    const float* kg = g_k + (size_t)bh * T_ * D_;
    const float* vg = g_v + (size_t)bh * T_ * D_;

    const int tid  = threadIdx.x;
    const int warp = tid >> 5;
    const int lane = tid & 31;
    const int gid  = lane >> 2;
    const int tig  = lane & 3;
    const int wm   = warp * 16;          // warp's row slab within 128
    const int qlr  = tid >> 1;           // Q stage: row 0..127
    const int qlc0 = (tid & 1) * 32;     // Q stage: column half
    const int klr  = tid >> 2;           // K/V stage: row 0..63
    const int kc0  = (tid & 3) * 16;     // K/V stage: column quarter

    // Stage Q tile (scaled, tf32) into Pst, pull A-fragments to registers
    #pragma unroll
    for (int g = 0; g < 8; g++) {
        const int c = qlc0 + g * 4;
        float4 qv = *(const float4*)(qg + (size_t)(qt * 128 + qlr) * D_ + c);
        float* p = &Pst[qlr * SP + c];
        p[0] = f2tf32(qv.x * 0.125f);
        p[1] = f2tf32(qv.y * 0.125f);
        p[2] = f2tf32(qv.z * 0.125f);
        p[3] = f2tf32(qv.w * 0.125f);
    }
    __syncthreads();

    unsigned qf[8][4];
    #pragma unroll
    for (int ks = 0; ks < 8; ks++) {
        qf[ks][0] = __float_as_uint(Pst[(wm + gid    ) * SP + ks * 8 + tig    ]);
        qf[ks][1] = __float_as_uint(Pst[(wm + gid + 8) * SP + ks * 8 + tig    ]);
        qf[ks][2] = __float_as_uint(Pst[(wm + gid    ) * SP + ks * 8 + tig + 4]);
        qf[ks][3] = __float_as_uint(Pst[(wm + gid + 8) * SP + ks * 8 + tig + 4]);
    }

    float oacc[8][4];
    #pragma unroll
    for (int j = 0; j < 8; j++)
        #pragma unroll
        for (int r = 0; r < 4; r++) oacc[j][r] = 0.0f;
    float m0 = -1e30f, m1 = -1e30f, l0 = 0.0f, l1 = 0.0f;

    const int row0 = qt * 128 + wm;      // warp's first global row
    const int nkt  = 2 * qt + 2;         // key tiles covering causal extent

    for (int kt = 0; kt < nkt; ++kt) {
        __syncthreads();  // prev-iter Kst/Vs readers done (also covers qf reads)
        #pragma unroll
        for (int g = 0; g < 4; g++) {
            const int c = kc0 + g * 4;
            float4 kv = *(const float4*)(kg + (size_t)(kt * 64 + klr) * D_ + c);
            Kst[(c + 0) * SP + klr] = f2tf32(kv.x);
            Kst[(c + 1) * SP + klr] = f2tf32(kv.y);
            Kst[(c + 2) * SP + klr] = f2tf32(kv.z);
            Kst[(c + 3) * SP + klr] = f2tf32(kv.w);
            float4 vv = *(const float4*)(vg + (size_t)(kt * 64 + klr) * D_ + c);
            float* p = &Vs[klr * SP + c];
            p[0] = f2tf32(vv.x);
            p[1] = f2tf32(vv.y);
            p[2] = f2tf32(vv.z);
            p[3] = f2tf32(vv.w);
        }
        __syncthreads();

        // warp-uniform skip: tile entirely above this warp's causal extent
        if (kt * 64 > row0 + 15) continue;

        // S = Q @ K^T
        float sacc[8][4];
        #pragma unroll
        for (int j = 0; j < 8; j++)
            #pragma unroll
            for (int r = 0; r < 4; r++) sacc[j][r] = 0.0f;

        #pragma unroll
        for (int ks = 0; ks < 8; ks++) {
            unsigned bf[8][2];
            #pragma unroll
            for (int j = 0; j < 8; j++) {
                bf[j][0] = __float_as_uint(Kst[(ks * 8 + tig    ) * SP + j * 8 + gid]);
                bf[j][1] = __float_as_uint(Kst[(ks * 8 + tig + 4) * SP + j * 8 + gid]);
            }
            #pragma unroll
            for (int j = 0; j < 8; j++)
                mma_tf32(sacc[j], qf[ks], bf[j]);
        }

        // causal mask (tiles overlapping this warp's diagonal)
        if (kt * 64 + 63 > row0) {
            #pragma unroll
            for (int j = 0; j < 8; j++) {
                const int cg = kt * 64 + j * 8 + 2 * tig;   // global col
                const int rg0 = row0 + gid;                  // global rows
                const int rg1 = row0 + gid + 8;
                if (cg     > rg0) sacc[j][0] = -1e30f;
                if (cg + 1 > rg0) sacc[j][1] = -1e30f;
                if (cg     > rg1) sacc[j][2] = -1e30f;
                if (cg + 1 > rg1) sacc[j][3] = -1e30f;
            }
        }

        // online softmax (rows gid and gid+8; reduction over tig lanes)
        float mt0 = -1e30f, mt1 = -1e30f;
        #pragma unroll
        for (int j = 0; j < 8; j++) {
            mt0 = fmaxf(mt0, fmaxf(sacc[j][0], sacc[j][1]));
            mt1 = fmaxf(mt1, fmaxf(sacc[j][2], sacc[j][3]));
        }
        mt0 = fmaxf(mt0, __shfl_xor_sync(0xffffffffu, mt0, 1));
        mt0 = fmaxf(mt0, __shfl_xor_sync(0xffffffffu, mt0, 2));
        mt1 = fmaxf(mt1, __shfl_xor_sync(0xffffffffu, mt1, 1));
        mt1 = fmaxf(mt1, __shfl_xor_sync(0xffffffffu, mt1, 2));

        const float mn0 = fmaxf(m0, mt0);
        const float mn1 = fmaxf(m1, mt1);
        const float a0 = __expf(m0 - mn0);
        const float a1 = __expf(m1 - mn1);
        float ls0 = 0.0f, ls1 = 0.0f;

        #pragma unroll
        for (int j = 0; j < 8; j++) {
            const float p00 = __expf(sacc[j][0] - mn0);
            const float p01 = __expf(sacc[j][1] - mn0);
            const float p10 = __expf(sacc[j][2] - mn1);
            const float p11 = __expf(sacc[j][3] - mn1);
            ls0 += p00 + p01;
            ls1 += p10 + p11;
            const int c = j * 8 + 2 * tig;
            Pst[(wm + gid    ) * SP + c    ] = f2tf32(p00);
            Pst[(wm + gid    ) * SP + c + 1] = f2tf32(p01);
            Pst[(wm + gid + 8) * SP + c    ] = f2tf32(p10);
            Pst[(wm + gid + 8) * SP + c + 1] = f2tf32(p11);
            oacc[j][0] *= a0; oacc[j][1] *= a0;
            oacc[j][2] *= a1; oacc[j][3] *= a1;
        }
        ls0 += __shfl_xor_sync(0xffffffffu, ls0, 1);
        ls0 += __shfl_xor_sync(0xffffffffu, ls0, 2);
        ls1 += __shfl_xor_sync(0xffffffffu, ls1, 1);
        ls1 += __shfl_xor_sync(0xffffffffu, ls1, 2);
        l0 = l0 * a0 + ls0;
        l1 = l1 * a1 + ls1;
        m0 = mn0;
        m1 = mn1;
        __syncwarp();  // P rows are warp-private

        // O += P @ V
        #pragma unroll
        for (int ks = 0; ks < 8; ks++) {
            unsigned af[4];
            af[0] = __float_as_uint(Pst[(wm + gid    ) * SP + ks * 8 + tig    ]);
            af[1] = __float_as_uint(Pst[(wm + gid + 8) * SP + ks * 8 + tig    ]);
            af[2] = __float_as_uint(Pst[(wm + gid    ) * SP + ks * 8 + tig + 4]);
            af[3] = __float_as_uint(Pst[(wm + gid + 8) * SP + ks * 8 + tig + 4]);
            unsigned bf[8][2];
            #pragma unroll
            for (int j = 0; j < 8; j++) {
                bf[j][0] = __float_as_uint(Vs[(ks * 8 + tig    ) * SP + j * 8 + gid]);
                bf[j][1] = __float_as_uint(Vs[(ks * 8 + tig + 4) * SP + j * 8 + gid]);
            }
            #pragma unroll
            for (int j = 0; j < 8; j++)
                mma_tf32(oacc[j], af, bf[j]);
        }
    }

    // epilogue: normalize, write [B, T, H, D]
    const float i0 = 1.0f / l0;
    const float i1 = 1.0f / l1;
    const int r0 = qt * 128 + wm + gid;
    #pragma unroll
    for (int j = 0; j < 8; j++) {
        const int c = j * 8 + 2 * tig;
        float2 v0 = make_float2(oacc[j][0] * i0, oacc[j][1] * i0);
        float2 v1 = make_float2(oacc[j][2] * i1, oacc[j][3] * i1);
        *(float2*)(g_att + ((size_t)(b * T_ + r0    ) * H_ + h) * D_ + c) = v0;
        *(float2*)(g_att + ((size_t)(b * T_ + r0 + 8) * H_ + h) * D_ + c) = v1;
    }
}

// ---------------------------------------------------------------------------
// Kernel 3: output projection. grid=(C/64, B*T/128), block=256
// ---------------------------------------------------------------------------
__global__ __launch_bounds__(256) void proj_kernel(const float* __restrict__ Wp,
                                                   const float* __restrict__ bp,
                                                   float* __restrict__ out)
{
    extern __shared__ float sm[];
    gemm128x64_tf32(g_att, HD_, Wp, C_, bp, out, C_, HD_,
                    blockIdx.y * 128, blockIdx.x * 64, sm);
}

// ---------------------------------------------------------------------------
extern "C" void kernel_launch(void* const* d_in, const int* in_sizes, int n_in,
                              void* d_out, int out_size)
{
    const float* x  = (const float*)d_in[0];
    const float* Wq = (const float*)d_in[1];
    const float* Wk = (const float*)d_in[2];
    const float* Wv = (const float*)d_in[3];
    const float* Wp = (const float*)d_in[4];
    const float* bp = (const float*)d_in[5];
    float* out = (float*)d_out;

    (void)in_sizes; (void)n_in; (void)out_size;

    cudaFuncSetAttribute(qkv_kernel,
                         cudaFuncAttributeMaxDynamicSharedMemorySize, GEMM_SMEM);
    cudaFuncSetAttribute(proj_kernel,
                         cudaFuncAttributeMaxDynamicSharedMemorySize, GEMM_SMEM);
    cudaFuncSetAttribute(attn_kernel,
                         cudaFuncAttributeMaxDynamicSharedMemorySize, ATTN_SMEM);

    // QKV projections (tensor cores, double-buffered)
    {
        dim3 grid(T_ / 128, B_ * H_, 3);
        qkv_kernel<<<grid, 256, GEMM_SMEM>>>(x, Wq, Wk, Wv);
    }

    // Attention (tensor cores, BQ=128, 72 KB smem)
    {
        dim3 grid(T_ / 128, B_ * H_);
        attn_kernel<<<grid, 256, ATTN_SMEM>>>();
    }

    // Output projection (tensor cores, double-buffered)
    {
        dim3 grid(C_ / 64, (B_ * T_) / 128);
        proj_kernel<<<grid, 256, GEMM_SMEM>>>(Wp, bp, out);
    }
}

// round 9
// speedup vs baseline: 1.5693x; 1.3721x over previous
#include <cuda_runtime.h>
#include <math.h>

#define B_ 4
#define T_ 1024
#define C_ 1024
#define H_ 16
#define D_ 64
#define HD_ (H_*D_)

// Scratch (allocation-free rule: __device__ globals)
__device__ float g_q[(size_t)B_*H_*T_*D_];
__device__ float g_k[(size_t)B_*H_*T_*D_];
__device__ float g_v[(size_t)B_*H_*T_*D_];
__device__ float g_att[(size_t)B_*T_*HD_];   // [B, T, H, D] = [B, T, HD]

// ---------------------------------------------------------------------------
__device__ __forceinline__ float f2tf32(float f) {
    unsigned u;
    asm("cvt.rna.tf32.f32 %0, %1;" : "=r"(u) : "f"(f));
    return __uint_as_float(u);
}

__device__ __forceinline__ void mma_tf32(float c[4], const unsigned a[4],
                                         const unsigned b[2]) {
    asm("mma.sync.aligned.m16n8k8.row.col.f32.tf32.tf32.f32 "
        "{%0,%1,%2,%3}, {%4,%5,%6,%7}, {%8,%9}, {%0,%1,%2,%3};"
        : "+f"(c[0]), "+f"(c[1]), "+f"(c[2]), "+f"(c[3])
        : "r"(a[0]), "r"(a[1]), "r"(a[2]), "r"(a[3]), "r"(b[0]), "r"(b[1]));
}

// ---------------------------------------------------------------------------
// TF32 GEMM, fragment-packed double-buffered smem.
// C[m0:+128, n0:+64] = A @ B (+bias). 256 threads, warp tile 32x32, BK=32.
//
// A fragment store: Af float4 slot s = (mi*4+ks)*32 + gid*4 + (tig^ks)
//   holds {A[mi*16+gid][ks*8+tig], A[mi*16+8+gid][ks*8+tig],
//          A[mi*16+gid][ks*8+tig+4], A[mi*16+8+gid][ks*8+tig+4]}
// B fragment store: Bf float2 slot = nj*BPLANE + ks*32 + gid*4 + tig
//   holds {B[ks*8+tig][nj*8+gid], B[ks*8+tig+4][nj*8+gid]}
// ---------------------------------------------------------------------------
#define AFRAG 4096            // floats per A buffer (8*4*32 float4)
#define BPLANE 133            // float2 per nj plane (128 + 5 pad)
#define BFRAG (8*BPLANE*2)    // floats per B buffer = 2128
#define GEMM_SMEM ((2*AFRAG + 2*BFRAG)*4)

__device__ __forceinline__ void stage_a(float* Abuf, const float4* areg,
                                        int tid)
{
    const int a_row = tid >> 3;
    const int ksA = (tid & 7) >> 1;
    const int compA_base = 2 * (tid & 1);
    #pragma unroll
    for (int i = 0; i < 4; i++) {
        const int r = a_row + 32 * i;
        const int mi = r >> 4;
        const int gidw = r & 7;
        const int compA = compA_base + ((r >> 3) & 1);
        const int base = (mi * 4 + ksA) * 32 + gidw * 4;
        float v[4] = {f2tf32(areg[i].x), f2tf32(areg[i].y),
                      f2tf32(areg[i].z), f2tf32(areg[i].w)};
        #pragma unroll
        for (int e = 0; e < 4; e++)
            Abuf[(base + (e ^ ksA)) * 4 + compA] = v[e];
    }
}

__device__ __forceinline__ void stage_b(float* Bbuf, const float4* breg,
                                        int tid)
{
    const int b_row = tid >> 4;
    const int njw = (tid & 15) >> 1;
    const int gidb0 = (tid & 1) * 4;
    #pragma unroll
    for (int i = 0; i < 2; i++) {
        const int kk = b_row + 16 * i;
        const int ksb = kk >> 3;
        const int tigb = kk & 3;
        const int compB = (kk >> 2) & 1;
        const int base2 = njw * BPLANE + ksb * 32 + tigb;
        float v[4] = {f2tf32(breg[i].x), f2tf32(breg[i].y),
                      f2tf32(breg[i].z), f2tf32(breg[i].w)};
        #pragma unroll
        for (int e = 0; e < 4; e++)
            Bbuf[(base2 + (gidb0 + e) * 4) * 2 + compB] = v[e];
    }
}

__device__ __forceinline__ void gemm128x64_tf32(
    const float* __restrict__ A, int lda,
    const float* __restrict__ Bm, int ldb,
    const float* __restrict__ bias,
    float* __restrict__ Cm, int ldc,
    int Kdim, int m0, int n0, float* sm)
{
    float* A0 = sm;                 // [2][AFRAG]
    float* B0 = sm + 2 * AFRAG;     // [2][BFRAG]

    const int tid  = threadIdx.x;
    const int warp = tid >> 5;
    const int lane = tid & 31;
    const int gid  = lane >> 2;
    const int tig  = lane & 3;
    const int mi0  = (warp >> 1) * 2;    // warp's first m16 tile
    const int nj0  = (warp & 1) * 4;     // warp's first n8 tile

    const int a_row = tid >> 3;
    const int a_cg  = (tid & 7) * 4;
    const int b_row = tid >> 4;
    const int b_cg  = (tid & 15) * 4;

    float4 areg[4], breg[2];

    // prefetch tile 0 and stage into buffer 0
    #pragma unroll
    for (int i = 0; i < 4; i++)
        areg[i] = *(const float4*)(A + (size_t)(m0 + a_row + 32 * i) * lda + a_cg);
    #pragma unroll
    for (int i = 0; i < 2; i++)
        breg[i] = *(const float4*)(Bm + (size_t)(b_row + 16 * i) * ldb + n0 + b_cg);
    stage_a(A0, areg, tid);
    stage_b(B0, breg, tid);
    __syncthreads();

    float acc[2][4][4];
    #pragma unroll
    for (int i = 0; i < 2; i++)
        #pragma unroll
        for (int j = 0; j < 4; j++)
            #pragma unroll
            for (int r = 0; r < 4; r++) acc[i][j][r] = 0.0f;

    for (int kt = 0; kt < Kdim; kt += 32) {
        const int cur = (kt >> 5) & 1;
        const bool more = (kt + 32 < Kdim);
        const float* Aa = A0 + cur * AFRAG;
        const float* Bb = B0 + cur * BFRAG;

        if (more) {
            #pragma unroll
            for (int i = 0; i < 4; i++)
                areg[i] = *(const float4*)(A + (size_t)(m0 + a_row + 32 * i) * lda + kt + 32 + a_cg);
            #pragma unroll
            for (int i = 0; i < 2; i++)
                breg[i] = *(const float4*)(Bm + (size_t)(kt + 32 + b_row + 16 * i) * ldb + n0 + b_cg);
        }

        #pragma unroll
        for (int ks = 0; ks < 4; ks++) {
            unsigned a[2][4], b[4][2];
            #pragma unroll
            for (int i = 0; i < 2; i++) {
                float4 v = *(const float4*)(Aa +
                    (((mi0 + i) * 4 + ks) * 32 + gid * 4 + (tig ^ ks)) * 4);
                a[i][0] = __float_as_uint(v.x);
                a[i][1] = __float_as_uint(v.y);
                a[i][2] = __float_as_uint(v.z);
                a[i][3] = __float_as_uint(v.w);
            }
            #pragma unroll
            for (int j = 0; j < 4; j++) {
                float2 v = *(const float2*)(Bb +
                    ((nj0 + j) * BPLANE + ks * 32 + gid * 4 + tig) * 2);
                b[j][0] = __float_as_uint(v.x);
                b[j][1] = __float_as_uint(v.y);
            }
            #pragma unroll
            for (int i = 0; i < 2; i++)
                #pragma unroll
                for (int j = 0; j < 4; j++)
                    mma_tf32(acc[i][j], a[i], b[j]);
        }

        if (more) {
            stage_a(A0 + (cur ^ 1) * AFRAG, areg, tid);
            stage_b(B0 + (cur ^ 1) * BFRAG, breg, tid);
        }
        __syncthreads();
    }

    // epilogue
    #pragma unroll
    for (int i = 0; i < 2; i++) {
        const int r = m0 + (mi0 + i) * 16 + gid;
        #pragma unroll
        for (int j = 0; j < 4; j++) {
            const int c = n0 + (nj0 + j) * 8 + 2 * tig;
            float bx = 0.f, by = 0.f;
            if (bias) { bx = bias[c]; by = bias[c + 1]; }
            float2 o0 = make_float2(acc[i][j][0] + bx, acc[i][j][1] + by);
            float2 o1 = make_float2(acc[i][j][2] + bx, acc[i][j][3] + by);
            *(float2*)(Cm + (size_t)r * ldc + c) = o0;
            *(float2*)(Cm + (size_t)(r + 8) * ldc + c) = o1;
        }
    }
}

// ---------------------------------------------------------------------------
// Kernel 1: QKV projections. grid=(T/128, B*H, 3), block=256
// ---------------------------------------------------------------------------
__global__ __launch_bounds__(256) void qkv_kernel(const float* __restrict__ x,
                                                  const float* __restrict__ Wq,
                                                  const float* __restrict__ Wk,
                                                  const float* __restrict__ Wv)
{
    extern __shared__ float sm[];
    const int bh = blockIdx.y;
    const int b = bh >> 4;
    const int h = bh & 15;
    const int which = blockIdx.z;
    const float* W = (which == 0 ? Wq : (which == 1 ? Wk : Wv)) + (size_t)h * C_ * D_;
    float* dst = (which == 0 ? g_q : (which == 1 ? g_k : g_v)) + (size_t)bh * T_ * D_;
    gemm128x64_tf32(x + (size_t)b * T_ * C_, C_, W, D_, nullptr, dst, D_, C_,
                    blockIdx.x * 128, 0, sm);
}

// ---------------------------------------------------------------------------
// Kernel 2: causal flash attention, tf32 m16n8k8, BQ=128 (8 warps).
// (unchanged from R8 — passing)
// ---------------------------------------------------------------------------
#define SP 72
#define ATTN_SMEM ((64*SP + 64*SP + 128*SP) * 4)

__global__ __launch_bounds__(256) void attn_kernel()
{
    extern __shared__ float sm[];
    float* Kst = sm;              // [64][SP]  Kst[d][s]
    float* Vs  = sm + 64 * SP;    // [64][SP]  Vs[s][d]
    float* Pst = sm + 128 * SP;   // [128][SP] P rows (also Q staging)

    const int qt = (int)gridDim.x - 1 - (int)blockIdx.x;  // long CTAs first
    const int bh = blockIdx.y;
    const int b = bh >> 4;
    const int h = bh & 15;
    const float* qg = g_q + (size_t)bh * T_ * D_;
    const float* kg = g_k + (size_t)bh * T_ * D_;
    const float* vg = g_v + (size_t)bh * T_ * D_;

    const int tid  = threadIdx.x;
    const int warp = tid >> 5;
    const int lane = tid & 31;
    const int gid  = lane >> 2;
    const int tig  = lane & 3;
    const int wm   = warp * 16;
    const int qlr  = tid >> 1;
    const int qlc0 = (tid & 1) * 32;
    const int klr  = tid >> 2;
    const int kc0  = (tid & 3) * 16;

    // Stage Q tile (scaled, tf32) into Pst, pull A-fragments to registers
    #pragma unroll
    for (int g = 0; g < 8; g++) {
        const int c = qlc0 + g * 4;
        float4 qv = *(const float4*)(qg + (size_t)(qt * 128 + qlr) * D_ + c);
        float* p = &Pst[qlr * SP + c];
        p[0] = f2tf32(qv.x * 0.125f);
        p[1] = f2tf32(qv.y * 0.125f);
        p[2] = f2tf32(qv.z * 0.125f);
        p[3] = f2tf32(qv.w * 0.125f);
    }
    __syncthreads();

    unsigned qf[8][4];
    #pragma unroll
    for (int ks = 0; ks < 8; ks++) {
        qf[ks][0] = __float_as_uint(Pst[(wm + gid    ) * SP + ks * 8 + tig    ]);
        qf[ks][1] = __float_as_uint(Pst[(wm + gid + 8) * SP + ks * 8 + tig    ]);
        qf[ks][2] = __float_as_uint(Pst[(wm + gid    ) * SP + ks * 8 + tig + 4]);
        qf[ks][3] = __float_as_uint(Pst[(wm + gid + 8) * SP + ks * 8 + tig + 4]);
    }

    float oacc[8][4];
    #pragma unroll
    for (int j = 0; j < 8; j++)
        #pragma unroll
        for (int r = 0; r < 4; r++) oacc[j][r] = 0.0f;
    float m0 = -1e30f, m1 = -1e30f, l0 = 0.0f, l1 = 0.0f;

    const int row0 = qt * 128 + wm;
    const int nkt  = 2 * qt + 2;

    for (int kt = 0; kt < nkt; ++kt) {
        __syncthreads();
        #pragma unroll
        for (int g = 0; g < 4; g++) {
            const int c = kc0 + g * 4;
            float4 kv = *(const float4*)(kg + (size_t)(kt * 64 + klr) * D_ + c);
            Kst[(c + 0) * SP + klr] = f2tf32(kv.x);
            Kst[(c + 1) * SP + klr] = f2tf32(kv.y);
            Kst[(c + 2) * SP + klr] = f2tf32(kv.z);
            Kst[(c + 3) * SP + klr] = f2tf32(kv.w);
            float4 vv = *(const float4*)(vg + (size_t)(kt * 64 + klr) * D_ + c);
            float* p = &Vs[klr * SP + c];
            p[0] = f2tf32(vv.x);
            p[1] = f2tf32(vv.y);
            p[2] = f2tf32(vv.z);
            p[3] = f2tf32(vv.w);
        }
        __syncthreads();

        if (kt * 64 > row0 + 15) continue;

        // S = Q @ K^T
        float sacc[8][4];
        #pragma unroll
        for (int j = 0; j < 8; j++)
            #pragma unroll
            for (int r = 0; r < 4; r++) sacc[j][r] = 0.0f;

        #pragma unroll
        for (int ks = 0; ks < 8; ks++) {
            unsigned bf[8][2];
            #pragma unroll
            for (int j = 0; j < 8; j++) {
                bf[j][0] = __float_as_uint(Kst[(ks * 8 + tig    ) * SP + j * 8 + gid]);
                bf[j][1] = __float_as_uint(Kst[(ks * 8 + tig + 4) * SP + j * 8 + gid]);
            }
            #pragma unroll
            for (int j = 0; j < 8; j++)
                mma_tf32(sacc[j], qf[ks], bf[j]);
        }

        // causal mask
        if (kt * 64 + 63 > row0) {
            #pragma unroll
            for (int j = 0; j < 8; j++) {
                const int cg = kt * 64 + j * 8 + 2 * tig;
                const int rg0 = row0 + gid;
                const int rg1 = row0 + gid + 8;
                if (cg     > rg0) sacc[j][0] = -1e30f;
                if (cg + 1 > rg0) sacc[j][1] = -1e30f;
                if (cg     > rg1) sacc[j][2] = -1e30f;
                if (cg + 1 > rg1) sacc[j][3] = -1e30f;
            }
        }

        // online softmax
        float mt0 = -1e30f, mt1 = -1e30f;
        #pragma unroll
        for (int j = 0; j < 8; j++) {
            mt0 = fmaxf(mt0, fmaxf(sacc[j][0], sacc[j][1]));
            mt1 = fmaxf(mt1, fmaxf(sacc[j][2], sacc[j][3]));
        }
        mt0 = fmaxf(mt0, __shfl_xor_sync(0xffffffffu, mt0, 1));
        mt0 = fmaxf(mt0, __shfl_xor_sync(0xffffffffu, mt0, 2));
        mt1 = fmaxf(mt1, __shfl_xor_sync(0xffffffffu, mt1, 1));
        mt1 = fmaxf(mt1, __shfl_xor_sync(0xffffffffu, mt1, 2));

        const float mn0 = fmaxf(m0, mt0);
        const float mn1 = fmaxf(m1, mt1);
        const float a0 = __expf(m0 - mn0);
        const float a1 = __expf(m1 - mn1);
        float ls0 = 0.0f, ls1 = 0.0f;

        #pragma unroll
        for (int j = 0; j < 8; j++) {
            const float p00 = __expf(sacc[j][0] - mn0);
            const float p01 = __expf(sacc[j][1] - mn0);
            const float p10 = __expf(sacc[j][2] - mn1);
            const float p11 = __expf(sacc[j][3] - mn1);
            ls0 += p00 + p01;
            ls1 += p10 + p11;
            const int c = j * 8 + 2 * tig;
            Pst[(wm + gid    ) * SP + c    ] = f2tf32(p00);
            Pst[(wm + gid    ) * SP + c + 1] = f2tf32(p01);
            Pst[(wm + gid + 8) * SP + c    ] = f2tf32(p10);
            Pst[(wm + gid + 8) * SP + c + 1] = f2tf32(p11);
            oacc[j][0] *= a0; oacc[j][1] *= a0;
            oacc[j][2] *= a1; oacc[j][3] *= a1;
        }
        ls0 += __shfl_xor_sync(0xffffffffu, ls0, 1);
        ls0 += __shfl_xor_sync(0xffffffffu, ls0, 2);
        ls1 += __shfl_xor_sync(0xffffffffu, ls1, 1);
        ls1 += __shfl_xor_sync(0xffffffffu, ls1, 2);
        l0 = l0 * a0 + ls0;
        l1 = l1 * a1 + ls1;
        m0 = mn0;
        m1 = mn1;
        __syncwarp();

        // O += P @ V
        #pragma unroll
        for (int ks = 0; ks < 8; ks++) {
            unsigned af[4];
            af[0] = __float_as_uint(Pst[(wm + gid    ) * SP + ks * 8 + tig    ]);
            af[1] = __float_as_uint(Pst[(wm + gid + 8) * SP + ks * 8 + tig    ]);
            af[2] = __float_as_uint(Pst[(wm + gid    ) * SP + ks * 8 + tig + 4]);
            af[3] = __float_as_uint(Pst[(wm + gid + 8) * SP + ks * 8 + tig + 4]);
            unsigned bf[8][2];
            #pragma unroll
            for (int j = 0; j < 8; j++) {
                bf[j][0] = __float_as_uint(Vs[(ks * 8 + tig    ) * SP + j * 8 + gid]);
                bf[j][1] = __float_as_uint(Vs[(ks * 8 + tig + 4) * SP + j * 8 + gid]);
            }
            #pragma unroll
            for (int j = 0; j < 8; j++)
                mma_tf32(oacc[j], af, bf[j]);
        }
    }

    // epilogue: normalize, write [B, T, H, D]
    const float i0 = 1.0f / l0;
    const float i1 = 1.0f / l1;
    const int r0 = qt * 128 + wm + gid;
    #pragma unroll
    for (int j = 0; j < 8; j++) {
        const int c = j * 8 + 2 * tig;
        float2 v0 = make_float2(oacc[j][0] * i0, oacc[j][1] * i0);
        float2 v1 = make_float2(oacc[j][2] * i1, oacc[j][3] * i1);
        *(float2*)(g_att + ((size_t)(b * T_ + r0    ) * H_ + h) * D_ + c) = v0;
        *(float2*)(g_att + ((size_t)(b * T_ + r0 + 8) * H_ + h) * D_ + c) = v1;
    }
}

// ---------------------------------------------------------------------------
// Kernel 3: output projection. grid=(C/64, B*T/128), block=256
// ---------------------------------------------------------------------------
__global__ __launch_bounds__(256) void proj_kernel(const float* __restrict__ Wp,
                                                   const float* __restrict__ bp,
                                                   float* __restrict__ out)
{
    extern __shared__ float sm[];
    gemm128x64_tf32(g_att, HD_, Wp, C_, bp, out, C_, HD_,
                    blockIdx.y * 128, blockIdx.x * 64, sm);
}

// ---------------------------------------------------------------------------
extern "C" void kernel_launch(void* const* d_in, const int* in_sizes, int n_in,
                              void* d_out, int out_size)
{
    const float* x  = (const float*)d_in[0];
    const float* Wq = (const float*)d_in[1];
    const float* Wk = (const float*)d_in[2];
    const float* Wv = (const float*)d_in[3];
    const float* Wp = (const float*)d_in[4];
    const float* bp = (const float*)d_in[5];
    float* out = (float*)d_out;

    (void)in_sizes; (void)n_in; (void)out_size;

    cudaFuncSetAttribute(qkv_kernel,
                         cudaFuncAttributeMaxDynamicSharedMemorySize, GEMM_SMEM);
    cudaFuncSetAttribute(proj_kernel,
                         cudaFuncAttributeMaxDynamicSharedMemorySize, GEMM_SMEM);
    cudaFuncSetAttribute(attn_kernel,
                         cudaFuncAttributeMaxDynamicSharedMemorySize, ATTN_SMEM);

    // QKV projections
    {
        dim3 grid(T_ / 128, B_ * H_, 3);
        qkv_kernel<<<grid, 256, GEMM_SMEM>>>(x, Wq, Wk, Wv);
    }

    // Attention (BQ=128)
    {
        dim3 grid(T_ / 128, B_ * H_);
        attn_kernel<<<grid, 256, ATTN_SMEM>>>();
    }

    // Output projection
    {
        dim3 grid(C_ / 64, (B_ * T_) / 128);
        proj_kernel<<<grid, 256, GEMM_SMEM>>>(Wp, bp, out);
    }
}

// round 11
// speedup vs baseline: 1.7786x; 1.1334x over previous
#include <cuda_runtime.h>
#include <math.h>

#define B_ 4
#define T_ 1024
#define C_ 1024
#define H_ 16
#define D_ 64
#define HD_ (H_*D_)

// Scratch (allocation-free rule: __device__ globals)
__device__ float g_q[(size_t)B_*H_*T_*D_];
__device__ float g_k[(size_t)B_*H_*T_*D_];
__device__ float g_v[(size_t)B_*H_*T_*D_];
__device__ float g_att[(size_t)B_*T_*HD_];   // [B, T, H, D] = [B, T, HD]

// ---------------------------------------------------------------------------
__device__ __forceinline__ float f2tf32(float f) {
    unsigned u;
    asm("cvt.rna.tf32.f32 %0, %1;" : "=r"(u) : "f"(f));
    return __uint_as_float(u);
}

__device__ __forceinline__ void mma_tf32(float c[4], const unsigned a[4],
                                         const unsigned b[2]) {
    asm("mma.sync.aligned.m16n8k8.row.col.f32.tf32.tf32.f32 "
        "{%0,%1,%2,%3}, {%4,%5,%6,%7}, {%8,%9}, {%0,%1,%2,%3};"
        : "+f"(c[0]), "+f"(c[1]), "+f"(c[2]), "+f"(c[3])
        : "r"(a[0]), "r"(a[1]), "r"(a[2]), "r"(a[3]), "r"(b[0]), "r"(b[1]));
}

// ---------------------------------------------------------------------------
// Fragment-packed staging (validated R9 layout).
// A: float4 slot (mi*4+ks)*32 + gid*4 + (tig^ks) -> one a-fragment.
// B: float2 slot nj*BPLANE + ks*32 + gid*4 + tig -> one b-fragment.
// ---------------------------------------------------------------------------
#define AFRAG 4096            // floats per A buffer (8*4*32 float4)
#define BPLANE 133            // float2 per nj plane (128 + 5 pad)
#define BFRAG (8*BPLANE*2)    // floats per B buffer = 2128
#define QKV_SMEM ((2*AFRAG + 6*BFRAG)*4)
#define GEMM_SMEM ((2*AFRAG + 2*BFRAG)*4)

__device__ __forceinline__ void stage_a(float* Abuf, const float4* areg,
                                        int tid)
{
    const int a_row = tid >> 3;
    const int ksA = (tid & 7) >> 1;
    const int compA_base = 2 * (tid & 1);
    #pragma unroll
    for (int i = 0; i < 4; i++) {
        const int r = a_row + 32 * i;
        const int mi = r >> 4;
        const int gidw = r & 7;
        const int compA = compA_base + ((r >> 3) & 1);
        const int base = (mi * 4 + ksA) * 32 + gidw * 4;
        float v[4] = {f2tf32(areg[i].x), f2tf32(areg[i].y),
                      f2tf32(areg[i].z), f2tf32(areg[i].w)};
        #pragma unroll
        for (int e = 0; e < 4; e++)
            Abuf[(base + (e ^ ksA)) * 4 + compA] = v[e];
    }
}

__device__ __forceinline__ void stage_b(float* Bbuf, const float4* breg,
                                        int tid)
{
    const int b_row = tid >> 4;
    const int njw = (tid & 15) >> 1;
    const int gidb0 = (tid & 1) * 4;
    #pragma unroll
    for (int i = 0; i < 2; i++) {
        const int kk = b_row + 16 * i;
        const int ksb = kk >> 3;
        const int tigb = kk & 3;
        const int compB = (kk >> 2) & 1;
        const int base2 = njw * BPLANE + ksb * 32 + tigb;
        float v[4] = {f2tf32(breg[i].x), f2tf32(breg[i].y),
                      f2tf32(breg[i].z), f2tf32(breg[i].w)};
        #pragma unroll
        for (int e = 0; e < 4; e++)
            Bbuf[(base2 + (gidb0 + e) * 4) * 2 + compB] = v[e];
    }
}

// ---------------------------------------------------------------------------
// Kernel 1: FUSED QKV. One CTA computes q,k,v 128x64 tiles for one (b,h,mt).
// A tile staged ONCE per K-step, reused for 3 weight matrices.
// grid=(T/128, B*H), block=256, smem=83.8KB, 1 CTA/SM.
// ---------------------------------------------------------------------------
__global__ __launch_bounds__(256, 1) void qkv_kernel(
    const float* __restrict__ x,
    const float* __restrict__ Wq,
    const float* __restrict__ Wk,
    const float* __restrict__ Wv)
{
    extern __shared__ float sm[];
    float* A0 = sm;                 // [2][AFRAG]
    float* B0 = sm + 2 * AFRAG;     // [2][3][BFRAG]

    const int bh = blockIdx.y;
    const int b = bh >> 4;
    const int h = bh & 15;
    const int m0 = blockIdx.x * 128;

    const float* A = x + (size_t)b * T_ * C_;
    const float* Wm[3] = {Wq + (size_t)h * C_ * D_,
                          Wk + (size_t)h * C_ * D_,
                          Wv + (size_t)h * C_ * D_};
    float* dst[3] = {g_q + (size_t)bh * T_ * D_,
                     g_k + (size_t)bh * T_ * D_,
                     g_v + (size_t)bh * T_ * D_};

    const int tid  = threadIdx.x;
    const int warp = tid >> 5;
    const int lane = tid & 31;
    const int gid  = lane >> 2;
    const int tig  = lane & 3;
    const int mi0  = (warp >> 1) * 2;
    const int nj0  = (warp & 1) * 4;

    const int a_row = tid >> 3;
    const int a_cg  = (tid & 7) * 4;
    const int b_row = tid >> 4;
    const int b_cg  = (tid & 15) * 4;

    float4 areg[4], breg[3][2];

    // prefetch tile 0, stage into buffer 0
    #pragma unroll
    for (int i = 0; i < 4; i++)
        areg[i] = *(const float4*)(A + (size_t)(m0 + a_row + 32 * i) * C_ + a_cg);
    #pragma unroll
    for (int m = 0; m < 3; m++)
        #pragma unroll
        for (int i = 0; i < 2; i++)
            breg[m][i] = *(const float4*)(Wm[m] + (size_t)(b_row + 16 * i) * D_ + b_cg);

    stage_a(A0, areg, tid);
    #pragma unroll
    for (int m = 0; m < 3; m++)
        stage_b(B0 + m * BFRAG, breg[m], tid);
    __syncthreads();

    float acc[3][2][4][4];
    #pragma unroll
    for (int m = 0; m < 3; m++)
        #pragma unroll
        for (int i = 0; i < 2; i++)
            #pragma unroll
            for (int j = 0; j < 4; j++)
                #pragma unroll
                for (int r = 0; r < 4; r++) acc[m][i][j][r] = 0.0f;

    for (int kt = 0; kt < C_; kt += 32) {
        const int cur = (kt >> 5) & 1;
        const bool more = (kt + 32 < C_);
        const float* Aa = A0 + cur * AFRAG;
        const float* Bb0 = B0 + (cur * 3    ) * BFRAG;
        const float* Bb1 = B0 + (cur * 3 + 1) * BFRAG;
        const float* Bb2 = B0 + (cur * 3 + 2) * BFRAG;

        if (more) {
            #pragma unroll
            for (int i = 0; i < 4; i++)
                areg[i] = *(const float4*)(A + (size_t)(m0 + a_row + 32 * i) * C_ + kt + 32 + a_cg);
            #pragma unroll
            for (int m = 0; m < 3; m++)
                #pragma unroll
                for (int i = 0; i < 2; i++)
                    breg[m][i] = *(const float4*)(Wm[m] + (size_t)(kt + 32 + b_row + 16 * i) * D_ + b_cg);
        }

        #pragma unroll
        for (int ks = 0; ks < 4; ks++) {
            unsigned a[2][4];
            #pragma unroll
            for (int i = 0; i < 2; i++) {
                float4 v = *(const float4*)(Aa +
                    (((mi0 + i) * 4 + ks) * 32 + gid * 4 + (tig ^ ks)) * 4);
                a[i][0] = __float_as_uint(v.x);
                a[i][1] = __float_as_uint(v.y);
                a[i][2] = __float_as_uint(v.z);
                a[i][3] = __float_as_uint(v.w);
            }
            const float* Bbs[3] = {Bb0, Bb1, Bb2};
            #pragma unroll
            for (int m = 0; m < 3; m++) {
                unsigned bfrag[4][2];
                #pragma unroll
                for (int j = 0; j < 4; j++) {
                    float2 v = *(const float2*)(Bbs[m] +
                        ((nj0 + j) * BPLANE + ks * 32 + gid * 4 + tig) * 2);
                    bfrag[j][0] = __float_as_uint(v.x);
                    bfrag[j][1] = __float_as_uint(v.y);
                }
                #pragma unroll
                for (int i = 0; i < 2; i++)
                    #pragma unroll
                    for (int j = 0; j < 4; j++)
                        mma_tf32(acc[m][i][j], a[i], bfrag[j]);
            }
        }

        if (more) {
            stage_a(A0 + (cur ^ 1) * AFRAG, areg, tid);
            #pragma unroll
            for (int m = 0; m < 3; m++)
                stage_b(B0 + ((cur ^ 1) * 3 + m) * BFRAG, breg[m], tid);
        }
        __syncthreads();
    }

    // epilogue: 3 outputs
    #pragma unroll
    for (int m = 0; m < 3; m++) {
        #pragma unroll
        for (int i = 0; i < 2; i++) {
            const int r = m0 + (mi0 + i) * 16 + gid;
            #pragma unroll
            for (int j = 0; j < 4; j++) {
                const int c = (nj0 + j) * 8 + 2 * tig;
                float2 o0 = make_float2(acc[m][i][j][0], acc[m][i][j][1]);
                float2 o1 = make_float2(acc[m][i][j][2], acc[m][i][j][3]);
                *(float2*)(dst[m] + (size_t)r * D_ + c) = o0;
                *(float2*)(dst[m] + (size_t)(r + 8) * D_ + c) = o1;
            }
        }
    }
}

// ---------------------------------------------------------------------------
// TF32 GEMM (R9, validated) — used by proj.
// ---------------------------------------------------------------------------
__device__ __forceinline__ void gemm128x64_tf32(
    const float* __restrict__ A, int lda,
    const float* __restrict__ Bm, int ldb,
    const float* __restrict__ bias,
    float* __restrict__ Cm, int ldc,
    int Kdim, int m0, int n0, float* sm)
{
    float* A0 = sm;
    float* B0 = sm + 2 * AFRAG;

    const int tid  = threadIdx.x;
    const int warp = tid >> 5;
    const int lane = tid & 31;
    const int gid  = lane >> 2;
    const int tig  = lane & 3;
    const int mi0  = (warp >> 1) * 2;
    const int nj0  = (warp & 1) * 4;

    const int a_row = tid >> 3;
    const int a_cg  = (tid & 7) * 4;
    const int b_row = tid >> 4;
    const int b_cg  = (tid & 15) * 4;

    float4 areg[4], breg[2];

    #pragma unroll
    for (int i = 0; i < 4; i++)
        areg[i] = *(const float4*)(A + (size_t)(m0 + a_row + 32 * i) * lda + a_cg);
    #pragma unroll
    for (int i = 0; i < 2; i++)
        breg[i] = *(const float4*)(Bm + (size_t)(b_row + 16 * i) * ldb + n0 + b_cg);
    stage_a(A0, areg, tid);
    stage_b(B0, breg, tid);
    __syncthreads();

    float acc[2][4][4];
    #pragma unroll
    for (int i = 0; i < 2; i++)
        #pragma unroll
        for (int j = 0; j < 4; j++)
            #pragma unroll
            for (int r = 0; r < 4; r++) acc[i][j][r] = 0.0f;

    for (int kt = 0; kt < Kdim; kt += 32) {
        const int cur = (kt >> 5) & 1;
        const bool more = (kt + 32 < Kdim);
        const float* Aa = A0 + cur * AFRAG;
        const float* Bb = B0 + cur * BFRAG;

        if (more) {
            #pragma unroll
            for (int i = 0; i < 4; i++)
                areg[i] = *(const float4*)(A + (size_t)(m0 + a_row + 32 * i) * lda + kt + 32 + a_cg);
            #pragma unroll
            for (int i = 0; i < 2; i++)
                breg[i] = *(const float4*)(Bm + (size_t)(kt + 32 + b_row + 16 * i) * ldb + n0 + b_cg);
        }

        #pragma unroll
        for (int ks = 0; ks < 4; ks++) {
            unsigned a[2][4], bb[4][2];
            #pragma unroll
            for (int i = 0; i < 2; i++) {
                float4 v = *(const float4*)(Aa +
                    (((mi0 + i) * 4 + ks) * 32 + gid * 4 + (tig ^ ks)) * 4);
                a[i][0] = __float_as_uint(v.x);
                a[i][1] = __float_as_uint(v.y);
                a[i][2] = __float_as_uint(v.z);
                a[i][3] = __float_as_uint(v.w);
            }
            #pragma unroll
            for (int j = 0; j < 4; j++) {
                float2 v = *(const float2*)(Bb +
                    ((nj0 + j) * BPLANE + ks * 32 + gid * 4 + tig) * 2);
                bb[j][0] = __float_as_uint(v.x);
                bb[j][1] = __float_as_uint(v.y);
            }
            #pragma unroll
            for (int i = 0; i < 2; i++)
                #pragma unroll
                for (int j = 0; j < 4; j++)
                    mma_tf32(acc[i][j], a[i], bb[j]);
        }

        if (more) {
            stage_a(A0 + (cur ^ 1) * AFRAG, areg, tid);
            stage_b(B0 + (cur ^ 1) * BFRAG, breg, tid);
        }
        __syncthreads();
    }

    #pragma unroll
    for (int i = 0; i < 2; i++) {
        const int r = m0 + (mi0 + i) * 16 + gid;
        #pragma unroll
        for (int j = 0; j < 4; j++) {
            const int c = n0 + (nj0 + j) * 8 + 2 * tig;
            float bx = 0.f, by = 0.f;
            if (bias) { bx = bias[c]; by = bias[c + 1]; }
            float2 o0 = make_float2(acc[i][j][0] + bx, acc[i][j][1] + by);
            float2 o1 = make_float2(acc[i][j][2] + bx, acc[i][j][3] + by);
            *(float2*)(Cm + (size_t)r * ldc + c) = o0;
            *(float2*)(Cm + (size_t)(r + 8) * ldc + c) = o1;
        }
    }
}

// ---------------------------------------------------------------------------
// Kernel 2: causal flash attention, tf32 m16n8k8, BQ=128 (8 warps).
// (unchanged from R8/R9 — passing)
// ---------------------------------------------------------------------------
#define SP 72
#define ATTN_SMEM ((64*SP + 64*SP + 128*SP) * 4)

__global__ __launch_bounds__(256) void attn_kernel()
{
    extern __shared__ float sm[];
    float* Kst = sm;              // [64][SP]  Kst[d][s]
    float* Vs  = sm + 64 * SP;    // [64][SP]  Vs[s][d]
    float* Pst = sm + 128 * SP;   // [128][SP] P rows (also Q staging)

    const int qt = (int)gridDim.x - 1 - (int)blockIdx.x;
    const int bh = blockIdx.y;
    const int b = bh >> 4;
    const int h = bh & 15;
    const float* qg = g_q + (size_t)bh * T_ * D_;
    const float* kg = g_k + (size_t)bh * T_ * D_;
    const float* vg = g_v + (size_t)bh * T_ * D_;

    const int tid  = threadIdx.x;
    const int warp = tid >> 5;
    const int lane = tid & 31;
    const int gid  = lane >> 2;
    const int tig  = lane & 3;
    const int wm   = warp * 16;
    const int qlr  = tid >> 1;
    const int qlc0 = (tid & 1) * 32;
    const int klr  = tid >> 2;
    const int kc0  = (tid & 3) * 16;

    #pragma unroll
    for (int g = 0; g < 8; g++) {
        const int c = qlc0 + g * 4;
        float4 qv = *(const float4*)(qg + (size_t)(qt * 128 + qlr) * D_ + c);
        float* p = &Pst[qlr * SP + c];
        p[0] = f2tf32(qv.x * 0.125f);
        p[1] = f2tf32(qv.y * 0.125f);
        p[2] = f2tf32(qv.z * 0.125f);
        p[3] = f2tf32(qv.w * 0.125f);
    }
    __syncthreads();

    unsigned qf[8][4];
    #pragma unroll
    for (int ks = 0; ks < 8; ks++) {
        qf[ks][0] = __float_as_uint(Pst[(wm + gid    ) * SP + ks * 8 + tig    ]);
        qf[ks][1] = __float_as_uint(Pst[(wm + gid + 8) * SP + ks * 8 + tig    ]);
        qf[ks][2] = __float_as_uint(Pst[(wm + gid    ) * SP + ks * 8 + tig + 4]);
        qf[ks][3] = __float_as_uint(Pst[(wm + gid + 8) * SP + ks * 8 + tig + 4]);
    }

    float oacc[8][4];
    #pragma unroll
    for (int j = 0; j < 8; j++)
        #pragma unroll
        for (int r = 0; r < 4; r++) oacc[j][r] = 0.0f;
    float m0 = -1e30f, m1 = -1e30f, l0 = 0.0f, l1 = 0.0f;

    const int row0 = qt * 128 + wm;
    const int nkt  = 2 * qt + 2;

    for (int kt = 0; kt < nkt; ++kt) {
        __syncthreads();
        #pragma unroll
        for (int g = 0; g < 4; g++) {
            const int c = kc0 + g * 4;
            float4 kv = *(const float4*)(kg + (size_t)(kt * 64 + klr) * D_ + c);
            Kst[(c + 0) * SP + klr] = f2tf32(kv.x);
            Kst[(c + 1) * SP + klr] = f2tf32(kv.y);
            Kst[(c + 2) * SP + klr] = f2tf32(kv.z);
            Kst[(c + 3) * SP + klr] = f2tf32(kv.w);
            float4 vv = *(const float4*)(vg + (size_t)(kt * 64 + klr) * D_ + c);
            float* p = &Vs[klr * SP + c];
            p[0] = f2tf32(vv.x);
            p[1] = f2tf32(vv.y);
            p[2] = f2tf32(vv.z);
            p[3] = f2tf32(vv.w);
        }
        __syncthreads();

        if (kt * 64 > row0 + 15) continue;

        float sacc[8][4];
        #pragma unroll
        for (int j = 0; j < 8; j++)
            #pragma unroll
            for (int r = 0; r < 4; r++) sacc[j][r] = 0.0f;

        #pragma unroll
        for (int ks = 0; ks < 8; ks++) {
            unsigned bf[8][2];
            #pragma unroll
            for (int j = 0; j < 8; j++) {
                bf[j][0] = __float_as_uint(Kst[(ks * 8 + tig    ) * SP + j * 8 + gid]);
                bf[j][1] = __float_as_uint(Kst[(ks * 8 + tig + 4) * SP + j * 8 + gid]);
            }
            #pragma unroll
            for (int j = 0; j < 8; j++)
                mma_tf32(sacc[j], qf[ks], bf[j]);
        }

        if (kt * 64 + 63 > row0) {
            #pragma unroll
            for (int j = 0; j < 8; j++) {
                const int cg = kt * 64 + j * 8 + 2 * tig;
                const int rg0 = row0 + gid;
                const int rg1 = row0 + gid + 8;
                if (cg     > rg0) sacc[j][0] = -1e30f;
                if (cg + 1 > rg0) sacc[j][1] = -1e30f;
                if (cg     > rg1) sacc[j][2] = -1e30f;
                if (cg + 1 > rg1) sacc[j][3] = -1e30f;
            }
        }

        float mt0 = -1e30f, mt1 = -1e30f;
        #pragma unroll
        for (int j = 0; j < 8; j++) {
            mt0 = fmaxf(mt0, fmaxf(sacc[j][0], sacc[j][1]));
            mt1 = fmaxf(mt1, fmaxf(sacc[j][2], sacc[j][3]));
        }
        mt0 = fmaxf(mt0, __shfl_xor_sync(0xffffffffu, mt0, 1));
        mt0 = fmaxf(mt0, __shfl_xor_sync(0xffffffffu, mt0, 2));
        mt1 = fmaxf(mt1, __shfl_xor_sync(0xffffffffu, mt1, 1));
        mt1 = fmaxf(mt1, __shfl_xor_sync(0xffffffffu, mt1, 2));

        const float mn0 = fmaxf(m0, mt0);
        const float mn1 = fmaxf(m1, mt1);
        const float a0 = __expf(m0 - mn0);
        const float a1 = __expf(m1 - mn1);
        float ls0 = 0.0f, ls1 = 0.0f;

        #pragma unroll
        for (int j = 0; j < 8; j++) {
            const float p00 = __expf(sacc[j][0] - mn0);
            const float p01 = __expf(sacc[j][1] - mn0);
            const float p10 = __expf(sacc[j][2] - mn1);
            const float p11 = __expf(sacc[j][3] - mn1);
            ls0 += p00 + p01;
            ls1 += p10 + p11;
            const int c = j * 8 + 2 * tig;
            Pst[(wm + gid    ) * SP + c    ] = f2tf32(p00);
            Pst[(wm + gid    ) * SP + c + 1] = f2tf32(p01);
            Pst[(wm + gid + 8) * SP + c    ] = f2tf32(p10);
            Pst[(wm + gid + 8) * SP + c + 1] = f2tf32(p11);
            oacc[j][0] *= a0; oacc[j][1] *= a0;
            oacc[j][2] *= a1; oacc[j][3] *= a1;
        }
        ls0 += __shfl_xor_sync(0xffffffffu, ls0, 1);
        ls0 += __shfl_xor_sync(0xffffffffu, ls0, 2);
        ls1 += __shfl_xor_sync(0xffffffffu, ls1, 1);
        ls1 += __shfl_xor_sync(0xffffffffu, ls1, 2);
        l0 = l0 * a0 + ls0;
        l1 = l1 * a1 + ls1;
        m0 = mn0;
        m1 = mn1;
        __syncwarp();

        #pragma unroll
        for (int ks = 0; ks < 8; ks++) {
            unsigned af[4];
            af[0] = __float_as_uint(Pst[(wm + gid    ) * SP + ks * 8 + tig    ]);
            af[1] = __float_as_uint(Pst[(wm + gid + 8) * SP + ks * 8 + tig    ]);
            af[2] = __float_as_uint(Pst[(wm + gid    ) * SP + ks * 8 + tig + 4]);
            af[3] = __float_as_uint(Pst[(wm + gid + 8) * SP + ks * 8 + tig + 4]);
            unsigned bf[8][2];
            #pragma unroll
            for (int j = 0; j < 8; j++) {
                bf[j][0] = __float_as_uint(Vs[(ks * 8 + tig    ) * SP + j * 8 + gid]);
                bf[j][1] = __float_as_uint(Vs[(ks * 8 + tig + 4) * SP + j * 8 + gid]);
            }
            #pragma unroll
            for (int j = 0; j < 8; j++)
                mma_tf32(oacc[j], af, bf[j]);
        }
    }

    const float i0 = 1.0f / l0;
    const float i1 = 1.0f / l1;
    const int r0 = qt * 128 + wm + gid;
    #pragma unroll
    for (int j = 0; j < 8; j++) {
        const int c = j * 8 + 2 * tig;
        float2 v0 = make_float2(oacc[j][0] * i0, oacc[j][1] * i0);
        float2 v1 = make_float2(oacc[j][2] * i1, oacc[j][3] * i1);
        *(float2*)(g_att + ((size_t)(b * T_ + r0    ) * H_ + h) * D_ + c) = v0;
        *(float2*)(g_att + ((size_t)(b * T_ + r0 + 8) * H_ + h) * D_ + c) = v1;
    }
}

// ---------------------------------------------------------------------------
// Kernel 3: output projection. grid=(C/64, B*T/128), block=256
// ---------------------------------------------------------------------------
__global__ __launch_bounds__(256) void proj_kernel(const float* __restrict__ Wp,
                                                   const float* __restrict__ bp,
                                                   float* __restrict__ out)
{
    extern __shared__ float sm[];
    gemm128x64_tf32(g_att, HD_, Wp, C_, bp, out, C_, HD_,
                    blockIdx.y * 128, blockIdx.x * 64, sm);
}

// ---------------------------------------------------------------------------
extern "C" void kernel_launch(void* const* d_in, const int* in_sizes, int n_in,
                              void* d_out, int out_size)
{
    const float* x  = (const float*)d_in[0];
    const float* Wq = (const float*)d_in[1];
    const float* Wk = (const float*)d_in[2];
    const float* Wv = (const float*)d_in[3];
    const float* Wp = (const float*)d_in[4];
    const float* bp = (const float*)d_in[5];
    float* out = (float*)d_out;

    (void)in_sizes; (void)n_in; (void)out_size;

    cudaFuncSetAttribute(qkv_kernel,
                         cudaFuncAttributeMaxDynamicSharedMemorySize, QKV_SMEM);
    cudaFuncSetAttribute(proj_kernel,
                         cudaFuncAttributeMaxDynamicSharedMemorySize, GEMM_SMEM);
    cudaFuncSetAttribute(attn_kernel,
                         cudaFuncAttributeMaxDynamicSharedMemorySize, ATTN_SMEM);

    // Fused QKV projections
    {
        dim3 grid(T_ / 128, B_ * H_);
        qkv_kernel<<<grid, 256, QKV_SMEM>>>(x, Wq, Wk, Wv);
    }

    // Attention (BQ=128)
    {
        dim3 grid(T_ / 128, B_ * H_);
        attn_kernel<<<grid, 256, ATTN_SMEM>>>();
    }

    // Output projection
    {
        dim3 grid(C_ / 64, (B_ * T_) / 128);
        proj_kernel<<<grid, 256, GEMM_SMEM>>>(Wp, bp, out);
    }
}